// round 17
// baseline (speedup 1.0000x reference)
// ============================================================================
// fNet_62285615727179 rev F17 — passing lineage (R16: 8025us, 5.8e-5).
// Latency-focused rev: flash-style single-pass GAT softmax, 4-way unrolled
// gathers (MLP=4), parallel scan. Dense: bf16 operands / fp32 accumulate.
// ============================================================================
#include <cuda_runtime.h>
#include <cuda_bf16.h>
#include <math.h>

namespace f17 {

constexpr int FN  = 100000;
constexpr int FE  = 1600000;
constexpr int FT  = FE + FN;
constexpr int FSB = 512;
constexpr int FSG = (FN + FSB - 1) / FSB;   // 196

__device__ int   fDeg[FN];
__device__ int   fCur[FN];
__device__ float fNrm[FN];
__device__ int   fIs64;
__device__ int   fSrc[FT];
__device__ int   fDst[FT];
__device__ int   fLoc[FN];
__device__ int   fTot[FSG];
__device__ int   fTotE[FSG];
__device__ int   fRow[FN + 1];
__device__ int   fAdj[FT];

__device__ float fH1[FN * 32];
__device__ float fG1[FN * 32];
__device__ float fH2[FN * 64];
__device__ float fG2[FN * 64];
__device__ float fH3[(size_t)FN * 128];
__device__ float fH4[FN * 2];
__device__ float fAs[FN];
__device__ float fAd[FN];

__device__ __forceinline__ float fLk(float x) { return x > 0.f ? x : 0.2f * x; }
__device__ __forceinline__ float fBf(float x) {
    return __bfloat162float(__float2bfloat16(x));
}

// ---- init: zero counters + dtype probe ----------------------------------------
__global__ void fkInit(const void* raw) {
    int i = blockIdx.x * blockDim.x + threadIdx.x;
    if (i < FN) { fDeg[i] = 0; fCur[i] = 0; }
    if (i == 0) {
        const int* p = (const int*)raw;
        int m = 0;
        for (int k = 1; k < 128; k += 2) m |= p[k];
        fIs64 = (m == 0);
    }
}

// ---- dense projection ----------------------------------------------------------
template <int CI, int CO, int RW, bool PRELU>
__global__ void fkProj(const float* __restrict__ in, const float* __restrict__ W,
                       const float* __restrict__ bias, float* __restrict__ out) {
    __shared__ float sw[CI * CO];
    __shared__ float sx[RW][CI];
    int flat = threadIdx.y * CO + threadIdx.x;
    for (int i = flat; i < CI * CO; i += CO * RW) sw[i] = fBf(W[i]);
    int n = blockIdx.x * RW + threadIdx.y;
    if (n < FN && threadIdx.x < CI) {
        float v = in[(size_t)n * CI + threadIdx.x];
        if (PRELU) v = fmaxf(v + bias[threadIdx.x], 0.f);
        sx[threadIdx.y][threadIdx.x] = fBf(v);
    }
    __syncthreads();
    if (n >= FN) return;
    float a = 0.f;
#pragma unroll
    for (int k = 0; k < CI; k++)
        a = fmaf(sx[threadIdx.y][k], sw[k * CO + threadIdx.x], a);
    out[(size_t)n * CO + threadIdx.x] = a;
}

// ---- graph assembly --------------------------------------------------------------
__global__ void fkDecode(const void* raw) {
    int e = blockIdx.x * blockDim.x + threadIdx.x;
    if (e >= FT) return;
    int s, d;
    if (e >= FE) {
        s = d = e - FE;
    } else if (fIs64) {
        const long long* p = (const long long*)raw;
        s = (int)p[e]; d = (int)p[FE + e];
    } else {
        const int* p = (const int*)raw;
        s = p[e]; d = p[FE + e];
    }
    fSrc[e] = s; fDst[e] = d;
    atomicAdd(&fDeg[d], 1);
}

__global__ void fkScanA() {
    __shared__ int sh[FSB];
    int t = threadIdx.x, i = blockIdx.x * FSB + t;
    int v = (i < FN) ? fDeg[i] : 0;
    sh[t] = v; __syncthreads();
    for (int o = 1; o < FSB; o <<= 1) {
        int u = (t >= o) ? sh[t - o] : 0; __syncthreads();
        sh[t] += u; __syncthreads();
    }
    if (i < FN) fLoc[i] = sh[t] - v;
    if (t == FSB - 1) fTot[blockIdx.x] = sh[t];
}

__global__ void fkScanB() {
    __shared__ int sh[256];
    int t = threadIdx.x;
    int v = (t < FSG) ? fTot[t] : 0;
    sh[t] = v; __syncthreads();
    for (int o = 1; o < 256; o <<= 1) {
        int u = (t >= o) ? sh[t - o] : 0; __syncthreads();
        sh[t] += u; __syncthreads();
    }
    if (t < FSG) fTotE[t] = sh[t] - v;
}

__global__ void fkScanC() {
    int i = blockIdx.x * blockDim.x + threadIdx.x;
    if (i < FN) {
        fRow[i] = fLoc[i] + fTotE[i / FSB];
        int dg = fDeg[i];
        fNrm[i] = dg > 0 ? rsqrtf((float)dg) : 0.f;
    }
    if (i == 0) fRow[FN] = FT;
}

__global__ void fkPlace() {
    int e = blockIdx.x * blockDim.x + threadIdx.x;
    if (e >= FT) return;
    int d = fDst[e];
    fAdj[fRow[d] + atomicAdd(&fCur[d], 1)] = fSrc[e];
}

// ---- GCN 32-ch gather: half-warp/node, 4-way unroll ------------------------------
__global__ void fkGcn32(const float* __restrict__ h, float* __restrict__ y) {
    int tid = blockIdx.x * blockDim.x + threadIdx.x;
    int n = tid >> 4, L = tid & 15;
    if (n >= FN) return;
    int lo = fRow[n], hi = fRow[n + 1];
    float me = fNrm[n];
    float a0 = 0.f, a1 = 0.f, b0 = 0.f, b1 = 0.f;
    float c0 = 0.f, c1 = 0.f, d0 = 0.f, d1 = 0.f;
    int i = lo;
    for (; i + 3 < hi; i += 4) {
        int s0 = __ldg(&fAdj[i]),     s1 = __ldg(&fAdj[i + 1]);
        int s2 = __ldg(&fAdj[i + 2]), s3 = __ldg(&fAdj[i + 3]);
        float f0 = __ldg(&fNrm[s0]) * me, f1 = __ldg(&fNrm[s1]) * me;
        float f2 = __ldg(&fNrm[s2]) * me, f3 = __ldg(&fNrm[s3]) * me;
        a0 = fmaf(f0, __ldg(&h[(size_t)s0 * 32 + L]), a0);
        a1 = fmaf(f0, __ldg(&h[(size_t)s0 * 32 + 16 + L]), a1);
        b0 = fmaf(f1, __ldg(&h[(size_t)s1 * 32 + L]), b0);
        b1 = fmaf(f1, __ldg(&h[(size_t)s1 * 32 + 16 + L]), b1);
        c0 = fmaf(f2, __ldg(&h[(size_t)s2 * 32 + L]), c0);
        c1 = fmaf(f2, __ldg(&h[(size_t)s2 * 32 + 16 + L]), c1);
        d0 = fmaf(f3, __ldg(&h[(size_t)s3 * 32 + L]), d0);
        d1 = fmaf(f3, __ldg(&h[(size_t)s3 * 32 + 16 + L]), d1);
    }
    for (; i < hi; i++) {
        int s = __ldg(&fAdj[i]);
        float f = __ldg(&fNrm[s]) * me;
        a0 = fmaf(f, __ldg(&h[(size_t)s * 32 + L]), a0);
        a1 = fmaf(f, __ldg(&h[(size_t)s * 32 + 16 + L]), a1);
    }
    y[(size_t)n * 32 + L] = (a0 + b0) + (c0 + d0);
    y[(size_t)n * 32 + 16 + L] = (a1 + b1) + (c1 + d1);
}

// ---- 32→64 projection + fused alpha scores ---------------------------------------
__global__ void fkProj64A(const float* __restrict__ in, const float* __restrict__ W,
                          const float* __restrict__ bias,
                          const float* __restrict__ aS, const float* __restrict__ aD,
                          float* __restrict__ out) {
    constexpr int CI = 32, CO = 64, RW = 4;
    __shared__ float sw[CI * CO];
    __shared__ float sx[RW][CI];
    __shared__ float red[RW][2][2];
    int tx = threadIdx.x, ty = threadIdx.y;
    int flat = ty * CO + tx;
    for (int i = flat; i < CI * CO; i += CO * RW) sw[i] = fBf(W[i]);
    int n = blockIdx.x * RW + ty;
    if (n < FN && tx < CI) {
        float v = fmaxf(in[(size_t)n * CI + tx] + bias[tx], 0.f);
        sx[ty][tx] = fBf(v);
    }
    __syncthreads();

    float a = 0.f;
    if (n < FN) {
#pragma unroll
        for (int k = 0; k < CI; k++)
            a = fmaf(sx[ty][k], sw[k * CO + tx], a);
        out[(size_t)n * CO + tx] = a;
    }
    float pS = (n < FN) ? fBf(a) * fBf(aS[tx]) : 0.f;
    float pD = (n < FN) ? fBf(a) * fBf(aD[tx]) : 0.f;
#pragma unroll
    for (int o = 16; o; o >>= 1) {
        pS += __shfl_xor_sync(~0u, pS, o);
        pD += __shfl_xor_sync(~0u, pD, o);
    }
    if ((tx & 31) == 0) {
        red[ty][tx >> 5][0] = pS;
        red[ty][tx >> 5][1] = pD;
    }
    __syncthreads();
    if (tx == 0 && n < FN) {
        fAs[n] = red[ty][0][0] + red[ty][1][0];
        fAd[n] = red[ty][0][1] + red[ty][1][1];
    }
}

// ---- GAT 64-ch: single-pass online softmax (flash recurrence), warp/node ---------
__global__ void fkGat64(const float2* __restrict__ h, float2* __restrict__ y) {
    __shared__ float sW[8][32];
    __shared__ int   sS[8][32];
    int wid = threadIdx.x >> 5;
    int n = (blockIdx.x * blockDim.x + threadIdx.x) >> 5;
    int L = threadIdx.x & 31;
    if (n >= FN) return;
    int lo = fRow[n], hi = fRow[n + 1];
    float cd = fAd[n];

    float m = -INFINITY, den = 0.f;
    float2 a = make_float2(0.f, 0.f), b = make_float2(0.f, 0.f);

    for (int base = lo; base < hi; base += 32) {
        int i = base + L;
        int s = (i < hi) ? __ldg(&fAdj[i]) : 0;
        float e = (i < hi) ? fLk(__ldg(&fAs[s]) + cd) : -INFINITY;
        float tm = e;
#pragma unroll
        for (int o = 16; o; o >>= 1) tm = fmaxf(tm, __shfl_xor_sync(~0u, tm, o));
        float nm = fmaxf(m, tm);
        float sc = expf(m - nm);                  // first tile: exp(-inf)=0, acc=0
        den *= sc;
        a.x *= sc; a.y *= sc; b.x *= sc; b.y *= sc;
        float w = (i < hi) ? expf(e - nm) : 0.f;
        sW[wid][L] = w; sS[wid][L] = s;
        float ws = w;
#pragma unroll
        for (int o = 16; o; o >>= 1) ws += __shfl_xor_sync(~0u, ws, o);
        den += ws;
        m = nm;
        __syncwarp();
        int cnt = min(32, hi - base);
        int j = 0;
        for (; j + 3 < cnt; j += 4) {
            int s0 = sS[wid][j],     s1 = sS[wid][j + 1];
            int s2 = sS[wid][j + 2], s3 = sS[wid][j + 3];
            float w0 = sW[wid][j],     w1 = sW[wid][j + 1];
            float w2 = sW[wid][j + 2], w3 = sW[wid][j + 3];
            float2 v0 = __ldg(&h[(size_t)s0 * 32 + L]);
            float2 v1 = __ldg(&h[(size_t)s1 * 32 + L]);
            float2 v2 = __ldg(&h[(size_t)s2 * 32 + L]);
            float2 v3 = __ldg(&h[(size_t)s3 * 32 + L]);
            a.x = fmaf(w0, v0.x, a.x); a.y = fmaf(w0, v0.y, a.y);
            b.x = fmaf(w1, v1.x, b.x); b.y = fmaf(w1, v1.y, b.y);
            a.x = fmaf(w2, v2.x, a.x); a.y = fmaf(w2, v2.y, a.y);
            b.x = fmaf(w3, v3.x, b.x); b.y = fmaf(w3, v3.y, b.y);
        }
        for (; j < cnt; j++) {
            int s0 = sS[wid][j];
            float w0 = sW[wid][j];
            float2 v0 = __ldg(&h[(size_t)s0 * 32 + L]);
            a.x = fmaf(w0, v0.x, a.x); a.y = fmaf(w0, v0.y, a.y);
        }
        __syncwarp();
    }
    float iv = 1.f / (den + 1e-16f);
    y[(size_t)n * 32 + L] = make_float2((a.x + b.x) * iv, (a.y + b.y) * iv);
}

// ---- FUSED 128-ch GCN gather + relu(+b3) + 128→2 head + alpha, 4-way unroll ------
__global__ void fkGatherHead(const float4* __restrict__ h3,
                             const float* __restrict__ W,
                             const float* __restrict__ b3,
                             const float* __restrict__ aS,
                             const float* __restrict__ aD) {
    int n = (blockIdx.x * blockDim.x + threadIdx.x) >> 5;
    int L = threadIdx.x & 31;
    if (n >= FN) return;
    int lo = fRow[n], hi = fRow[n + 1];
    float me = fNrm[n];

    float4 a = make_float4(0.f, 0.f, 0.f, 0.f);
    float4 b = make_float4(0.f, 0.f, 0.f, 0.f);
    int i = lo;
    for (; i + 3 < hi; i += 4) {
        int s0 = __ldg(&fAdj[i]),     s1 = __ldg(&fAdj[i + 1]);
        int s2 = __ldg(&fAdj[i + 2]), s3 = __ldg(&fAdj[i + 3]);
        float f0 = __ldg(&fNrm[s0]) * me, f1 = __ldg(&fNrm[s1]) * me;
        float f2 = __ldg(&fNrm[s2]) * me, f3 = __ldg(&fNrm[s3]) * me;
        float4 v0 = __ldg(&h3[(size_t)s0 * 32 + L]);
        float4 v1 = __ldg(&h3[(size_t)s1 * 32 + L]);
        float4 v2 = __ldg(&h3[(size_t)s2 * 32 + L]);
        float4 v3 = __ldg(&h3[(size_t)s3 * 32 + L]);
        a.x = fmaf(f0, v0.x, a.x); a.y = fmaf(f0, v0.y, a.y);
        a.z = fmaf(f0, v0.z, a.z); a.w = fmaf(f0, v0.w, a.w);
        b.x = fmaf(f1, v1.x, b.x); b.y = fmaf(f1, v1.y, b.y);
        b.z = fmaf(f1, v1.z, b.z); b.w = fmaf(f1, v1.w, b.w);
        a.x = fmaf(f2, v2.x, a.x); a.y = fmaf(f2, v2.y, a.y);
        a.z = fmaf(f2, v2.z, a.z); a.w = fmaf(f2, v2.w, a.w);
        b.x = fmaf(f3, v3.x, b.x); b.y = fmaf(f3, v3.y, b.y);
        b.z = fmaf(f3, v3.z, b.z); b.w = fmaf(f3, v3.w, b.w);
    }
    for (; i < hi; i++) {
        int s = __ldg(&fAdj[i]);
        float f = __ldg(&fNrm[s]) * me;
        float4 v = __ldg(&h3[(size_t)s * 32 + L]);
        a.x = fmaf(f, v.x, a.x); a.y = fmaf(f, v.y, a.y);
        a.z = fmaf(f, v.z, a.z); a.w = fmaf(f, v.w, a.w);
    }
    a.x += b.x; a.y += b.y; a.z += b.z; a.w += b.w;

    float4 bb = ((const float4*)b3)[L];
    float v[4] = {a.x + bb.x, a.y + bb.y, a.z + bb.z, a.w + bb.w};
    float c0 = 0.f, c1 = 0.f;
#pragma unroll
    for (int j = 0; j < 4; j++) {
        float w = fBf(fmaxf(v[j], 0.f));
        int k = L * 4 + j;
        c0 = fmaf(w, fBf(W[k * 2 + 0]), c0);
        c1 = fmaf(w, fBf(W[k * 2 + 1]), c1);
    }
#pragma unroll
    for (int o = 16; o; o >>= 1) {
        c0 += __shfl_xor_sync(~0u, c0, o);
        c1 += __shfl_xor_sync(~0u, c1, o);
    }
    if (L == 0) {
        fH4[n * 2 + 0] = c0;
        fH4[n * 2 + 1] = c1;
        fAs[n] = fBf(c0) * fBf(aS[0]) + fBf(c1) * fBf(aS[1]);
        fAd[n] = fBf(c0) * fBf(aD[0]) + fBf(c1) * fBf(aD[1]);
    }
}

// ---- GAT 2-ch + log_softmax: per-lane online softmax, half-warp/node -------------
__global__ void fkGat2Emit(const float* __restrict__ b4, float* __restrict__ out) {
    int tid = blockIdx.x * blockDim.x + threadIdx.x;
    int n = tid >> 4;
    int L = tid & 15;
    if (n >= FN) return;
    int lo = fRow[n], hi = fRow[n + 1];
    float cd = fAd[n];
    const unsigned HM = 0xFFFFu << (threadIdx.x & 16);

    // per-lane online softmax accumulation over its edge subset
    float m = -INFINITY, den = 0.f, p = 0.f, q = 0.f;
    for (int i = lo + L; i < hi; i += 16) {
        int s = __ldg(&fAdj[i]);
        float e = fLk(__ldg(&fAs[s]) + cd);
        float nm = fmaxf(m, e);
        float sc = expf(m - nm);       // first edge: exp(-inf)=0
        float w = expf(e - nm);
        den = den * sc + w;
        p = p * sc + w * __ldg(&fH4[s * 2 + 0]);
        q = q * sc + w * __ldg(&fH4[s * 2 + 1]);
        m = nm;
    }
    // merge lanes: global max, rescale, reduce
    float gm = m;
#pragma unroll
    for (int o = 8; o; o >>= 1) gm = fmaxf(gm, __shfl_xor_sync(HM, gm, o));
    float sc = expf(m - gm);           // lanes with no edges: m=-inf → sc=0
    den *= sc; p *= sc; q *= sc;
#pragma unroll
    for (int o = 8; o; o >>= 1) {
        den += __shfl_xor_sync(HM, den, o);
        p += __shfl_xor_sync(HM, p, o);
        q += __shfl_xor_sync(HM, q, o);
    }
    if (L == 0) {
        float iv = 1.f / (den + 1e-16f);
        float v0 = p * iv + b4[0];
        float v1 = q * iv + b4[1];
        float mm = fmaxf(v0, v1);
        float z = mm + logf(expf(v0 - mm) + expf(v1 - mm));
        out[n * 2 + 0] = v0 - z;
        out[n * 2 + 1] = v1 - z;
    }
}

}  // namespace f17

static inline int fcd(int a, int b) { return (a + b - 1) / b; }

extern "C" void kernel_launch(void* const* d_in, const int* in_sizes, int n_in,
                              void* d_out, int out_size) {
    using namespace f17;
    const float* x  = (const float*)d_in[0];
    const void*  ei = d_in[1];
    const float* W1 = (const float*)d_in[2];
    const float* b1 = (const float*)d_in[3];
    const float* W2 = (const float*)d_in[4];
    const float* s2 = (const float*)d_in[5];
    const float* d2 = (const float*)d_in[6];
    const float* b2 = (const float*)d_in[7];
    const float* W3 = (const float*)d_in[8];
    const float* b3 = (const float*)d_in[9];
    const float* W4 = (const float*)d_in[10];
    const float* s4 = (const float*)d_in[11];
    const float* d4 = (const float*)d_in[12];
    const float* b4 = (const float*)d_in[13];
    float* out = (float*)d_out;

    fkInit<<<fcd(FN, 512), 512>>>(ei);
    fkProj<7, 32, 8, false><<<fcd(FN, 8), dim3(32, 8)>>>(x, W1, nullptr, fH1);
    fkDecode<<<fcd(FT, 256), 256>>>(ei);
    fkScanA<<<FSG, FSB>>>();
    fkScanB<<<1, 256>>>();
    fkScanC<<<fcd(FN, 256), 256>>>();
    fkPlace<<<fcd(FT, 256), 256>>>();

    fkGcn32<<<fcd(FN * 16, 256), 256>>>(fH1, fG1);
    fkProj64A<<<fcd(FN, 4), dim3(64, 4)>>>(fG1, W2, b1, s2, d2, fH2);
    fkGat64<<<fcd(FN * 32, 256), 256>>>((const float2*)fH2, (float2*)fG2);
    fkProj<64, 128, 2, true><<<fcd(FN, 2), dim3(128, 2)>>>(fG2, W3, b2, fH3);
    fkGatherHead<<<fcd(FN * 32, 256), 256>>>((const float4*)fH3, W4, b3, s4, d4);
    fkGat2Emit<<<fcd(FN * 16, 256), 256>>>(b4, out);
}